// round 1
// baseline (speedup 1.0000x reference)
#include <cuda_runtime.h>
#include <math.h>

// Problem dims
#define LNUM 9
#define BDIM 8
#define SA 512
#define SB 512
#define EDIM 1024
#define HNUM 16
#define DHEAD 64
#define FDIM 4096
#define MROWS (BDIM*SA)          // 4096

// ---------------- scratch (device globals: no allocation allowed) ----------
__device__ float g_A  [MROWS*EDIM];
__device__ float g_A1 [MROWS*EDIM];
__device__ float g_Q  [MROWS*EDIM];
__device__ float g_K  [BDIM*SB*EDIM];
__device__ float g_V  [BDIM*SB*EDIM];
__device__ float g_S  [(long)BDIM*HNUM*SA*SB];   // 128 MB
__device__ float g_CTX[MROWS*EDIM];
__device__ float g_TMP[MROWS*EDIM];
__device__ float g_MID[(long)MROWS*FDIM];        // 64 MB
__device__ float g_PART[1024];

// ---------------- simple copy ----------------------------------------------
__global__ void copy_f(const float* __restrict__ src, float* __restrict__ dst, int n) {
    int i = blockIdx.x * blockDim.x + threadIdx.x;
    if (i < n) dst[i] = src[i];
}

// ---------------- generic strided-batched TN GEMM --------------------------
// C[m,n] = alpha * sum_k A[m*lda+k]*B[n*ldb+k] + bias[n]   (optionally relu)
// batch index bz -> (bb = bz/nH, hh = bz%nH); base += bb*s?b + hh*s?h
// BM=BN=128, BK=16, 256 threads, 8x8 per thread. All M,N mult of 128, K mult of 16.
__global__ void __launch_bounds__(256, 2) gemm_tn(
    const float* __restrict__ Ag, const float* __restrict__ Bg,
    const float* __restrict__ bias, float* __restrict__ Cg,
    int K, int lda, int ldb, int ldc,
    long sAb, long sAh, long sBb, long sBh, long sCb, long sCh, int nH,
    float alpha, int relu)
{
    int bz = blockIdx.z;
    int bb = bz / nH, hh = bz % nH;
    const float* A = Ag + bb * sAb + hh * sAh;
    const float* B = Bg + bb * sBb + hh * sBh;
    float*       C = Cg + bb * sCb + hh * sCh;
    int bm = blockIdx.y * 128, bn = blockIdx.x * 128;

    __shared__ float As[16][128];
    __shared__ float Bs[16][128];

    int tid = threadIdx.x;
    int m0 = (tid >> 4) << 3;        // 0..120
    int n0 = (tid & 15) << 3;        // 0..120

    float acc[8][8];
#pragma unroll
    for (int i = 0; i < 8; i++)
#pragma unroll
        for (int j = 0; j < 8; j++) acc[i][j] = 0.f;

    for (int kt = 0; kt < K; kt += 16) {
#pragma unroll
        for (int i = 0; i < 2; i++) {
            int idx = tid + i * 256;
            int row = idx >> 2;
            int kc  = (idx & 3) << 2;
            float4 va = *(const float4*)(A + (long)(bm + row) * lda + kt + kc);
            As[kc+0][row] = va.x; As[kc+1][row] = va.y;
            As[kc+2][row] = va.z; As[kc+3][row] = va.w;
            float4 vb = *(const float4*)(B + (long)(bn + row) * ldb + kt + kc);
            Bs[kc+0][row] = vb.x; Bs[kc+1][row] = vb.y;
            Bs[kc+2][row] = vb.z; Bs[kc+3][row] = vb.w;
        }
        __syncthreads();
#pragma unroll
        for (int k = 0; k < 16; k++) {
            float a[8], b[8];
            *(float4*)(a)     = *(const float4*)&As[k][m0];
            *(float4*)(a + 4) = *(const float4*)&As[k][m0 + 4];
            *(float4*)(b)     = *(const float4*)&Bs[k][n0];
            *(float4*)(b + 4) = *(const float4*)&Bs[k][n0 + 4];
#pragma unroll
            for (int i = 0; i < 8; i++)
#pragma unroll
                for (int j = 0; j < 8; j++)
                    acc[i][j] = fmaf(a[i], b[j], acc[i][j]);
        }
        __syncthreads();
    }

    float bv[8];
    if (bias) {
        *(float4*)(bv)     = *(const float4*)&bias[bn + n0];
        *(float4*)(bv + 4) = *(const float4*)&bias[bn + n0 + 4];
    } else {
#pragma unroll
        for (int j = 0; j < 8; j++) bv[j] = 0.f;
    }
#pragma unroll
    for (int i = 0; i < 8; i++) {
        long ro = (long)(bm + m0 + i) * ldc + bn + n0;
#pragma unroll
        for (int j = 0; j < 8; j += 4) {
            float4 v;
            v.x = acc[i][j+0] * alpha + bv[j+0];
            v.y = acc[i][j+1] * alpha + bv[j+1];
            v.z = acc[i][j+2] * alpha + bv[j+2];
            v.w = acc[i][j+3] * alpha + bv[j+3];
            if (relu) {
                v.x = fmaxf(v.x, 0.f); v.y = fmaxf(v.y, 0.f);
                v.z = fmaxf(v.z, 0.f); v.w = fmaxf(v.w, 0.f);
            }
            *(float4*)(C + ro + j) = v;
        }
    }
}

// ---------------- NN GEMM for ctx = attn @ V (BM=64, BN=64, BK=16) ---------
// C[m,n] = sum_k A[m*lda+k] * B[k*ldb+n]
__global__ void __launch_bounds__(256) gemm_nn64(
    const float* __restrict__ Ag, const float* __restrict__ Bg,
    float* __restrict__ Cg,
    int K, int lda, int ldb, int ldc,
    long sAb, long sAh, long sBb, long sBh, long sCb, long sCh, int nH)
{
    int bz = blockIdx.z;
    int bb = bz / nH, hh = bz % nH;
    const float* A = Ag + bb * sAb + hh * sAh;
    const float* B = Bg + bb * sBb + hh * sBh;
    float*       C = Cg + bb * sCb + hh * sCh;
    int bm = blockIdx.y * 64, bn = blockIdx.x * 64;

    __shared__ float As[64][17];
    __shared__ float Bs[16][64];

    int tid = threadIdx.x;
    int m0 = (tid >> 4) << 2;
    int n0 = (tid & 15) << 2;
    float acc[4][4];
#pragma unroll
    for (int i = 0; i < 4; i++)
#pragma unroll
        for (int j = 0; j < 4; j++) acc[i][j] = 0.f;

    for (int kt = 0; kt < K; kt += 16) {
        {
            int row = tid >> 2, kc = (tid & 3) << 2;
            float4 va = *(const float4*)(A + (long)(bm + row) * lda + kt + kc);
            As[row][kc+0] = va.x; As[row][kc+1] = va.y;
            As[row][kc+2] = va.z; As[row][kc+3] = va.w;
            int kr = tid >> 4, c4 = (tid & 15) << 2;
            float4 vb = *(const float4*)(B + (long)(kt + kr) * ldb + bn + c4);
            Bs[kr][c4+0] = vb.x; Bs[kr][c4+1] = vb.y;
            Bs[kr][c4+2] = vb.z; Bs[kr][c4+3] = vb.w;
        }
        __syncthreads();
#pragma unroll
        for (int k = 0; k < 16; k++) {
            float a[4], b[4];
            a[0] = As[m0+0][k]; a[1] = As[m0+1][k];
            a[2] = As[m0+2][k]; a[3] = As[m0+3][k];
            b[0] = Bs[k][n0+0]; b[1] = Bs[k][n0+1];
            b[2] = Bs[k][n0+2]; b[3] = Bs[k][n0+3];
#pragma unroll
            for (int i = 0; i < 4; i++)
#pragma unroll
                for (int j = 0; j < 4; j++)
                    acc[i][j] = fmaf(a[i], b[j], acc[i][j]);
        }
        __syncthreads();
    }
#pragma unroll
    for (int i = 0; i < 4; i++) {
        long ro = (long)(bm + m0 + i) * ldc + bn + n0;
        float4 v; v.x = acc[i][0]; v.y = acc[i][1]; v.z = acc[i][2]; v.w = acc[i][3];
        *(float4*)(C + ro) = v;
    }
}

// ---------------- softmax over rows of length 512 ---------------------------
__global__ void softmax512(float* __restrict__ S) {
    float* p = S + (long)blockIdx.x * 512;
    int t = threadIdx.x;
    float x0 = p[t], x1 = p[t + 256];
    __shared__ float red[256];
    float m = fmaxf(x0, x1);
    red[t] = m; __syncthreads();
    for (int s = 128; s > 0; s >>= 1) {
        if (t < s) red[t] = fmaxf(red[t], red[t + s]);
        __syncthreads();
    }
    m = red[0]; __syncthreads();
    float e0 = expf(x0 - m), e1 = expf(x1 - m);
    red[t] = e0 + e1; __syncthreads();
    for (int s = 128; s > 0; s >>= 1) {
        if (t < s) red[t] += red[t + s];
        __syncthreads();
    }
    float inv = 1.f / red[0];
    p[t] = e0 * inv;
    p[t + 256] = e1 * inv;
}

// ---------------- fused residual-add + LayerNorm (row = 1024) ---------------
__global__ void add_ln(const float* __restrict__ X, const float* __restrict__ R,
                       const float* __restrict__ g, const float* __restrict__ b,
                       float* __restrict__ Y)
{
    long row = blockIdx.x;
    const float* x = X + row * EDIM;
    const float* r = R + row * EDIM;
    float* y = Y + row * EDIM;
    int t = threadIdx.x;
    float v[4];
#pragma unroll
    for (int i = 0; i < 4; i++) v[i] = x[t + i*256] + r[t + i*256];
    __shared__ float red[256];
    red[t] = v[0] + v[1] + v[2] + v[3]; __syncthreads();
    for (int s = 128; s > 0; s >>= 1) { if (t < s) red[t] += red[t+s]; __syncthreads(); }
    float mean = red[0] * (1.f / EDIM); __syncthreads();
    float q = 0.f;
#pragma unroll
    for (int i = 0; i < 4; i++) { float d = v[i] - mean; q = fmaf(d, d, q); }
    red[t] = q; __syncthreads();
    for (int s = 128; s > 0; s >>= 1) { if (t < s) red[t] += red[t+s]; __syncthreads(); }
    float inv = rsqrtf(red[0] * (1.f / EDIM) + 1e-5f);
#pragma unroll
    for (int i = 0; i < 4; i++) {
        int c = t + i*256;
        y[c] = (v[i] - mean) * inv * g[c] + b[c];
    }
}

// ---------------- classifier + per-block partial loss sums ------------------
__global__ void classify(const float* __restrict__ Aout, const float* __restrict__ cw,
                         const float* __restrict__ cb, const int* __restrict__ labels,
                         const int* __restrict__ maskA, const int* __restrict__ cand,
                         float* __restrict__ outp, float* __restrict__ part)
{
    int warp = threadIdx.x >> 5, lane = threadIdx.x & 31;
    int row = blockIdx.x * 8 + warp;
    const float* a = Aout + (long)row * EDIM;
    float d0 = 0.f, d1 = 0.f;
    for (int e = lane; e < EDIM; e += 32) {
        float av = a[e];
        d0 = fmaf(av, cw[e], d0);
        d1 = fmaf(av, cw[EDIM + e], d1);
    }
#pragma unroll
    for (int o = 16; o > 0; o >>= 1) {
        d0 += __shfl_down_sync(0xffffffffu, d0, o);
        d1 += __shfl_down_sync(0xffffffffu, d1, o);
    }
    __shared__ float pw[8][2];
    if (lane == 0) {
        float e0 = d0 + cb[0], e1 = d1 + cb[1];
        int lb = labels[row];
        float mx = fmaxf(e0, e1);
        float lse = mx + logf(expf(e0 - mx) + expf(e1 - mx));
        float ce = lse - ((lb == 1) ? e1 : e0);
        float w = (lb == 1) ? 5.0f : 1.0f;
        float valid = (maskA[row] == 1) ? 1.0f : 0.0f;
        pw[warp][0] = ce * w * valid;
        pw[warp][1] = valid;
        int pred1 = (e1 > e0) ? 1 : 0;       // argmax with tie -> index 0
        outp[1 + row] = ((cand[row] == 1) && pred1) ? 1.0f : 0.0f;
    }
    __syncthreads();
    if (threadIdx.x == 0) {
        float s0 = 0.f, s1 = 0.f;
#pragma unroll
        for (int i = 0; i < 8; i++) { s0 += pw[i][0]; s1 += pw[i][1]; }
        part[blockIdx.x * 2 + 0] = s0;
        part[blockIdx.x * 2 + 1] = s1;
    }
}

__global__ void finalize(const float* __restrict__ part, float* __restrict__ outp) {
    __shared__ float r0[512], r1[512];
    int t = threadIdx.x;
    r0[t] = part[t * 2 + 0];
    r1[t] = part[t * 2 + 1];
    __syncthreads();
    for (int s = 256; s > 0; s >>= 1) {
        if (t < s) { r0[t] += r0[t+s]; r1[t] += r1[t+s]; }
        __syncthreads();
    }
    if (t == 0) outp[0] = r0[0] / fmaxf(r1[0], 1.0f);
}

// ---------------- host orchestration ----------------------------------------
extern "C" void kernel_launch(void* const* d_in, const int* in_sizes, int n_in,
                              void* d_out, int out_size)
{
    const float* enc   = (const float*)d_in[0];
    const float* dsc   = (const float*)d_in[1];
    const int*   maskA = (const int*)  d_in[2];
    const int*   cand  = (const int*)  d_in[3];
    const int*   labels= (const int*)  d_in[4];
    const float* ipw   = (const float*)d_in[5];
    const float* ipb   = (const float*)d_in[6];
    const float* ow    = (const float*)d_in[7];
    const float* ob    = (const float*)d_in[8];
    const float* g1    = (const float*)d_in[9];
    const float* b1    = (const float*)d_in[10];
    const float* W1    = (const float*)d_in[11];
    const float* bb1   = (const float*)d_in[12];
    const float* W2    = (const float*)d_in[13];
    const float* bb2   = (const float*)d_in[14];
    const float* g2    = (const float*)d_in[15];
    const float* b2    = (const float*)d_in[16];
    const float* cw    = (const float*)d_in[17];
    const float* cb    = (const float*)d_in[18];

    float *A, *A1, *Q, *Kb, *V, *S, *CTX, *TMP, *MID, *PART;
    cudaGetSymbolAddress((void**)&A,   g_A);
    cudaGetSymbolAddress((void**)&A1,  g_A1);
    cudaGetSymbolAddress((void**)&Q,   g_Q);
    cudaGetSymbolAddress((void**)&Kb,  g_K);
    cudaGetSymbolAddress((void**)&V,   g_V);
    cudaGetSymbolAddress((void**)&S,   g_S);
    cudaGetSymbolAddress((void**)&CTX, g_CTX);
    cudaGetSymbolAddress((void**)&TMP, g_TMP);
    cudaGetSymbolAddress((void**)&MID, g_MID);
    cudaGetSymbolAddress((void**)&PART,g_PART);

    // A <- encoded_matrix
    copy_f<<<(MROWS*EDIM + 255)/256, 256>>>(enc, A, MROWS*EDIM);

    const float scale = 0.125f;   // 1/sqrt(64)
    dim3 gP(EDIM/128, MROWS/128, 1);     // (8, 32)
    dim3 gF1(FDIM/128, MROWS/128, 1);    // (32, 32)
    dim3 gS(SB/128, SA/128, BDIM*HNUM);  // (4, 4, 128)
    dim3 gC(1, SA/64, BDIM*HNUM);        // (1, 8, 128)

    for (int l = 0; l < LNUM; l++) {
        const float* wq = ipw + (long)l * 3 * EDIM * EDIM;
        const float* wk = wq + (long)EDIM * EDIM;
        const float* wv = wk + (long)EDIM * EDIM;
        const float* bq = ipb + (long)l * 3 * EDIM;
        const float* bk = bq + EDIM;
        const float* bv = bk + EDIM;

        // Q = A @ wq^T + bq ; K = dsc @ wk^T + bk ; V = dsc @ wv^T + bv
        gemm_tn<<<gP, 256>>>(A,   wq, bq, Q,  EDIM, EDIM, EDIM, EDIM,
                             0,0,0,0,0,0,1, 1.0f, 0);
        gemm_tn<<<gP, 256>>>(dsc, wk, bk, Kb, EDIM, EDIM, EDIM, EDIM,
                             0,0,0,0,0,0,1, 1.0f, 0);
        gemm_tn<<<gP, 256>>>(dsc, wv, bv, V,  EDIM, EDIM, EDIM, EDIM,
                             0,0,0,0,0,0,1, 1.0f, 0);

        // scores[bh] = scale * Q_bh @ K_bh^T   (M=512, N=512, K=64)
        gemm_tn<<<gS, 256>>>(Q, Kb, (const float*)0, S, DHEAD, EDIM, EDIM, SB,
                             (long)SA*EDIM, DHEAD,
                             (long)SB*EDIM, DHEAD,
                             (long)HNUM*SA*SB, (long)SA*SB, HNUM,
                             scale, 0);

        softmax512<<<BDIM*HNUM*SA, 256>>>(S);

        // ctx[bh] = attn_bh @ V_bh   (M=512, N=64, K=512)
        gemm_nn64<<<gC, 256>>>(S, V, CTX, SB, SB, EDIM, EDIM,
                               (long)HNUM*SA*SB, (long)SA*SB,
                               (long)SB*EDIM, DHEAD,
                               (long)SA*EDIM, DHEAD, HNUM);

        // attn_out = ctx @ ow^T + ob
        gemm_tn<<<gP, 256>>>(CTX, ow + (long)l*EDIM*EDIM, ob + (long)l*EDIM, TMP,
                             EDIM, EDIM, EDIM, EDIM, 0,0,0,0,0,0,1, 1.0f, 0);

        // A1 = LN(A + attn_out)
        add_ln<<<MROWS, 256>>>(A, TMP, g1 + (long)l*EDIM, b1 + (long)l*EDIM, A1);

        // mid = relu(A1 @ W1^T + b1)
        gemm_tn<<<gF1, 256>>>(A1, W1 + (long)l*FDIM*EDIM, bb1 + (long)l*FDIM, MID,
                              EDIM, EDIM, EDIM, FDIM, 0,0,0,0,0,0,1, 1.0f, 1);

        // ff = mid @ W2^T + b2
        gemm_tn<<<gP, 256>>>(MID, W2 + (long)l*EDIM*FDIM, bb2 + (long)l*EDIM, TMP,
                             FDIM, FDIM, FDIM, EDIM, 0,0,0,0,0,0,1, 1.0f, 0);

        // A = LN(A1 + ff)
        add_ln<<<MROWS, 256>>>(A1, TMP, g2 + (long)l*EDIM, b2 + (long)l*EDIM, A);
    }

    classify<<<MROWS/8, 256>>>(A, cw, cb, labels, maskA, cand, (float*)d_out, PART);
    finalize<<<1, 512>>>(PART, (float*)d_out);
}

// round 2
// speedup vs baseline: 1.7609x; 1.7609x over previous
#include <cuda_runtime.h>
#include <cuda_bf16.h>
#include <math.h>

// Problem dims
#define LNUM 9
#define BDIM 8
#define SAQ 512
#define SBK 512
#define EDIM 1024
#define HNUM 16
#define DHEAD 64
#define FDIM 4096
#define MROWS (BDIM*SAQ)          // 4096

typedef __nv_bfloat16 bf16;
typedef __nv_bfloat162 bf162;

// ---------------- scratch (device globals) ----------------------------------
__device__ float g_A  [MROWS*EDIM];
__device__ float g_A1 [MROWS*EDIM];
__device__ float g_TMP[MROWS*EDIM];
__device__ float g_V  [MROWS*EDIM];
__device__ float g_S  [(long)BDIM*HNUM*SAQ*SBK];   // 134 MB
__device__ float g_PART[1024];

__device__ bf16 g_Ahi [MROWS*EDIM],  g_Alo [MROWS*EDIM];
__device__ bf16 g_A1hi[MROWS*EDIM],  g_A1lo[MROWS*EDIM];
__device__ bf16 g_Dhi [BDIM*SBK*EDIM], g_Dlo [BDIM*SBK*EDIM];
__device__ bf16 g_Qhi [MROWS*EDIM],  g_Qlo [MROWS*EDIM];
__device__ bf16 g_Khi [MROWS*EDIM],  g_Klo [MROWS*EDIM];
__device__ bf16 g_VThi[EDIM*MROWS],  g_VTlo[EDIM*MROWS];
__device__ bf16 g_Phi [(long)BDIM*HNUM*SAQ*SBK], g_Plo[(long)BDIM*HNUM*SAQ*SBK];
__device__ bf16 g_CThi[MROWS*EDIM],  g_CTlo[MROWS*EDIM];
__device__ bf16 g_MIDhi[(long)MROWS*FDIM], g_MIDlo[(long)MROWS*FDIM];
__device__ bf16 g_IPWhi[LNUM*3*EDIM*EDIM], g_IPWlo[LNUM*3*EDIM*EDIM];
__device__ bf16 g_OWhi [LNUM*EDIM*EDIM],   g_OWlo [LNUM*EDIM*EDIM];
__device__ bf16 g_W1hi [(long)LNUM*FDIM*EDIM], g_W1lo[(long)LNUM*FDIM*EDIM];
__device__ bf16 g_W2hi [(long)LNUM*EDIM*FDIM], g_W2lo[(long)LNUM*EDIM*FDIM];

// ---------------- helpers ----------------------------------------------------
__device__ __forceinline__ void split2(float v, bf16& h, bf16& l) {
    h = __float2bfloat16(v);
    l = __float2bfloat16(v - __bfloat162float(h));
}

__global__ void copy_f(const float* __restrict__ src, float* __restrict__ dst, int n) {
    int i = blockIdx.x * blockDim.x + threadIdx.x;
    if (i < n) dst[i] = src[i];
}

__global__ void split_f(const float* __restrict__ src, bf16* __restrict__ hi,
                        bf16* __restrict__ lo, int n) {
    int i = blockIdx.x * blockDim.x + threadIdx.x;
    if (i < n) { bf16 h, l; split2(src[i], h, l); hi[i] = h; lo[i] = l; }
}

// V [4096][1024] f32 -> VT [1024][4096] split bf16
__global__ void transpose_split(const float* __restrict__ V,
                                bf16* __restrict__ VThi, bf16* __restrict__ VTlo) {
    __shared__ float t[32][33];
    int bx = blockIdx.x * 32;   // E dim
    int by = blockIdx.y * 32;   // M dim
    int tx = threadIdx.x, ty = threadIdx.y;
#pragma unroll
    for (int i = 0; i < 4; i++)
        t[ty + i*8][tx] = V[(long)(by + ty + i*8) * EDIM + bx + tx];
    __syncthreads();
#pragma unroll
    for (int i = 0; i < 4; i++) {
        float v = t[tx][ty + i*8];
        bf16 h, l; split2(v, h, l);
        long o = (long)(bx + ty + i*8) * MROWS + by + tx;
        VThi[o] = h; VTlo[o] = l;
    }
}

// ---------------- bf16x3 warp-MMA GEMM (TN) ---------------------------------
// C[m,n] = alpha * sum_k (Ahi+Alo)[m,k] * (Bhi+Blo)[n,k]  (+bias, relu)
// dropping the Alo*Blo term. BM=128, BK=32, BN template (128 or 64).
// mode 0: store fp32 to Cf.   mode 1: split-store bf16 to Chi/Clo.
__device__ __forceinline__ void mma16816(float* d, const unsigned* a, const unsigned* b) {
    asm volatile(
        "mma.sync.aligned.m16n8k16.row.col.f32.bf16.bf16.f32 "
        "{%0,%1,%2,%3},{%4,%5,%6,%7},{%8,%9},{%0,%1,%2,%3};"
        : "+f"(d[0]), "+f"(d[1]), "+f"(d[2]), "+f"(d[3])
        : "r"(a[0]), "r"(a[1]), "r"(a[2]), "r"(a[3]), "r"(b[0]), "r"(b[1]));
}

template<int BN>
__global__ void __launch_bounds__(256) gemm_bf3(
    const bf16* __restrict__ Ahi_g, const bf16* __restrict__ Alo_g,
    const bf16* __restrict__ Bhi_g, const bf16* __restrict__ Blo_g,
    const float* __restrict__ bias,
    float* __restrict__ Cf, bf16* __restrict__ Chi, bf16* __restrict__ Clo,
    int K, int lda, int ldb, int ldc,
    long sAb, long sAh, long sBb, long sBh, long sCb, long sCh, int nH,
    float alpha, int mode, int relu)
{
    constexpr int KS = 40;            // padded smem row stride (bf16)
    constexpr int NT = BN / 16;       // n-tiles (m16n8) per warp
    __shared__ bf16 sA[2][128 * KS];
    __shared__ bf16 sB[2][BN * KS];

    int bz = blockIdx.z;
    int bb = bz / nH, hh = bz % nH;
    const bf16* Ah = Ahi_g + bb * sAb + hh * sAh;
    const bf16* Al = Alo_g + bb * sAb + hh * sAh;
    const bf16* Bh = Bhi_g + bb * sBb + hh * sBh;
    const bf16* Bl = Blo_g + bb * sBb + hh * sBh;
    long cbase = bb * sCb + hh * sCh;

    int bm = blockIdx.y * 128, bn = blockIdx.x * BN;
    int tid = threadIdx.x;
    int wid = tid >> 5, lane = tid & 31;
    int wm = wid & 3, wn = wid >> 2;
    int mb = wm * 32, nb = wn * (BN / 2);
    int lr = lane >> 2, lc = (lane & 3) * 2;

    float acc[2][NT][4];
#pragma unroll
    for (int i = 0; i < 2; i++)
#pragma unroll
        for (int j = 0; j < NT; j++)
#pragma unroll
            for (int q = 0; q < 4; q++) acc[i][j][q] = 0.f;

    for (int kt = 0; kt < K; kt += 32) {
        // ---- load A tiles (hi+lo): 128 rows x 32 cols, 16B chunks ----
#pragma unroll
        for (int c = tid; c < 128 * 4; c += 256) {
            int row = c >> 2, seg = (c & 3) * 8;
            long go = (long)(bm + row) * lda + kt + seg;
            int so = row * KS + seg;
            *(uint4*)&sA[0][so] = *(const uint4*)(Ah + go);
            *(uint4*)&sA[1][so] = *(const uint4*)(Al + go);
        }
        // ---- load B tiles (hi+lo): BN rows x 32 cols ----
#pragma unroll
        for (int c = tid; c < BN * 4; c += 256) {
            int row = c >> 2, seg = (c & 3) * 8;
            long go = (long)(bn + row) * ldb + kt + seg;
            int so = row * KS + seg;
            *(uint4*)&sB[0][so] = *(const uint4*)(Bh + go);
            *(uint4*)&sB[1][so] = *(const uint4*)(Bl + go);
        }
        __syncthreads();

#pragma unroll
        for (int ks = 0; ks < 2; ks++) {
            int k0 = ks * 16;
            unsigned aH[2][4], aL[2][4];
#pragma unroll
            for (int mt = 0; mt < 2; mt++) {
                int o = (mb + mt * 16 + lr) * KS + k0 + lc;
                aH[mt][0] = *(unsigned*)&sA[0][o];
                aH[mt][1] = *(unsigned*)&sA[0][o + 8 * KS];
                aH[mt][2] = *(unsigned*)&sA[0][o + 8];
                aH[mt][3] = *(unsigned*)&sA[0][o + 8 * KS + 8];
                aL[mt][0] = *(unsigned*)&sA[1][o];
                aL[mt][1] = *(unsigned*)&sA[1][o + 8 * KS];
                aL[mt][2] = *(unsigned*)&sA[1][o + 8];
                aL[mt][3] = *(unsigned*)&sA[1][o + 8 * KS + 8];
            }
#pragma unroll
            for (int nc = 0; nc < NT; nc += 4) {
                unsigned bH[4][2], bL[4][2];
#pragma unroll
                for (int j = 0; j < 4; j++) {
                    int o = (nb + (nc + j) * 8 + lr) * KS + k0 + lc;
                    bH[j][0] = *(unsigned*)&sB[0][o];
                    bH[j][1] = *(unsigned*)&sB[0][o + 8];
                    bL[j][0] = *(unsigned*)&sB[1][o];
                    bL[j][1] = *(unsigned*)&sB[1][o + 8];
                }
#pragma unroll
                for (int mt = 0; mt < 2; mt++)
#pragma unroll
                    for (int j = 0; j < 4; j++) {
                        mma16816(acc[mt][nc + j], aH[mt], bH[j]);   // hi*hi
                        mma16816(acc[mt][nc + j], aH[mt], bL[j]);   // hi*lo
                        mma16816(acc[mt][nc + j], aL[mt], bH[j]);   // lo*hi
                    }
            }
        }
        __syncthreads();
    }

    // ---- epilogue ----
#pragma unroll
    for (int mt = 0; mt < 2; mt++) {
#pragma unroll
        for (int nt = 0; nt < NT; nt++) {
            int gm = bm + mb + mt * 16 + lr;
            int gn = bn + nb + nt * 8 + lc;
            float v0 = acc[mt][nt][0] * alpha;
            float v1 = acc[mt][nt][1] * alpha;
            float v2 = acc[mt][nt][2] * alpha;
            float v3 = acc[mt][nt][3] * alpha;
            if (bias) {
                float b0 = bias[gn], b1 = bias[gn + 1];
                v0 += b0; v1 += b1; v2 += b0; v3 += b1;
            }
            if (relu) {
                v0 = fmaxf(v0, 0.f); v1 = fmaxf(v1, 0.f);
                v2 = fmaxf(v2, 0.f); v3 = fmaxf(v3, 0.f);
            }
            long o0 = cbase + (long)gm * ldc + gn;
            long o1 = cbase + (long)(gm + 8) * ldc + gn;
            if (mode == 0) {
                float2 r0; r0.x = v0; r0.y = v1;
                float2 r1; r1.x = v2; r1.y = v3;
                *(float2*)(Cf + o0) = r0;
                *(float2*)(Cf + o1) = r1;
            } else {
                bf16 h0, l0, h1, l1;
                split2(v0, h0, l0); split2(v1, h1, l1);
                *(bf162*)(Chi + o0) = __halves2bfloat162(h0, h1);
                *(bf162*)(Clo + o0) = __halves2bfloat162(l0, l1);
                split2(v2, h0, l0); split2(v3, h1, l1);
                *(bf162*)(Chi + o1) = __halves2bfloat162(h0, h1);
                *(bf162*)(Clo + o1) = __halves2bfloat162(l0, l1);
            }
        }
    }
}

// ---------------- softmax over rows of 512 -> split bf16 --------------------
__global__ void softmax512(const float* __restrict__ S,
                           bf16* __restrict__ Phi, bf16* __restrict__ Plo) {
    const float* p = S + (long)blockIdx.x * 512;
    int t = threadIdx.x;
    float x0 = p[t], x1 = p[t + 256];
    __shared__ float red[256];
    red[t] = fmaxf(x0, x1); __syncthreads();
    for (int s = 128; s > 0; s >>= 1) {
        if (t < s) red[t] = fmaxf(red[t], red[t + s]);
        __syncthreads();
    }
    float m = red[0]; __syncthreads();
    float e0 = expf(x0 - m), e1 = expf(x1 - m);
    red[t] = e0 + e1; __syncthreads();
    for (int s = 128; s > 0; s >>= 1) {
        if (t < s) red[t] += red[t + s];
        __syncthreads();
    }
    float inv = 1.f / red[0];
    long o = (long)blockIdx.x * 512 + t;
    bf16 h, l;
    split2(e0 * inv, h, l); Phi[o] = h;       Plo[o] = l;
    split2(e1 * inv, h, l); Phi[o + 256] = h; Plo[o + 256] = l;
}

// ---------------- fused residual + LayerNorm (+ split outputs) --------------
__global__ void add_ln(const float* __restrict__ X, const float* __restrict__ R,
                       const float* __restrict__ g, const float* __restrict__ b,
                       float* __restrict__ Y, bf16* __restrict__ Yhi, bf16* __restrict__ Ylo)
{
    long row = blockIdx.x;
    const float* x = X + row * EDIM;
    const float* r = R + row * EDIM;
    int t = threadIdx.x;
    float v[4];
#pragma unroll
    for (int i = 0; i < 4; i++) v[i] = x[t + i*256] + r[t + i*256];
    __shared__ float red[256];
    red[t] = v[0] + v[1] + v[2] + v[3]; __syncthreads();
    for (int s = 128; s > 0; s >>= 1) { if (t < s) red[t] += red[t+s]; __syncthreads(); }
    float mean = red[0] * (1.f / EDIM); __syncthreads();
    float q = 0.f;
#pragma unroll
    for (int i = 0; i < 4; i++) { float d = v[i] - mean; q = fmaf(d, d, q); }
    red[t] = q; __syncthreads();
    for (int s = 128; s > 0; s >>= 1) { if (t < s) red[t] += red[t+s]; __syncthreads(); }
    float inv = rsqrtf(red[0] * (1.f / EDIM) + 1e-5f);
#pragma unroll
    for (int i = 0; i < 4; i++) {
        int c = t + i*256;
        float y = (v[i] - mean) * inv * g[c] + b[c];
        Y[row * EDIM + c] = y;
        bf16 h, l; split2(y, h, l);
        Yhi[row * EDIM + c] = h;
        Ylo[row * EDIM + c] = l;
    }
}

// ---------------- classifier + loss ------------------------------------------
__global__ void classify(const float* __restrict__ Aout, const float* __restrict__ cw,
                         const float* __restrict__ cb, const int* __restrict__ labels,
                         const int* __restrict__ maskA, const int* __restrict__ cand,
                         float* __restrict__ outp, float* __restrict__ part)
{
    int warp = threadIdx.x >> 5, lane = threadIdx.x & 31;
    int row = blockIdx.x * 8 + warp;
    const float* a = Aout + (long)row * EDIM;
    float d0 = 0.f, d1 = 0.f;
    for (int e = lane; e < EDIM; e += 32) {
        float av = a[e];
        d0 = fmaf(av, cw[e], d0);
        d1 = fmaf(av, cw[EDIM + e], d1);
    }
#pragma unroll
    for (int o = 16; o > 0; o >>= 1) {
        d0 += __shfl_down_sync(0xffffffffu, d0, o);
        d1 += __shfl_down_sync(0xffffffffu, d1, o);
    }
    __shared__ float pw[8][2];
    if (lane == 0) {
        float e0 = d0 + cb[0], e1 = d1 + cb[1];
        int lb = labels[row];
        float mx = fmaxf(e0, e1);
        float lse = mx + logf(expf(e0 - mx) + expf(e1 - mx));
        float ce = lse - ((lb == 1) ? e1 : e0);
        float w = (lb == 1) ? 5.0f : 1.0f;
        float valid = (maskA[row] == 1) ? 1.0f : 0.0f;
        pw[warp][0] = ce * w * valid;
        pw[warp][1] = valid;
        int pred1 = (e1 > e0) ? 1 : 0;
        outp[1 + row] = ((cand[row] == 1) && pred1) ? 1.0f : 0.0f;
    }
    __syncthreads();
    if (threadIdx.x == 0) {
        float s0 = 0.f, s1 = 0.f;
#pragma unroll
        for (int i = 0; i < 8; i++) { s0 += pw[i][0]; s1 += pw[i][1]; }
        part[blockIdx.x * 2 + 0] = s0;
        part[blockIdx.x * 2 + 1] = s1;
    }
}

__global__ void finalize(const float* __restrict__ part, float* __restrict__ outp) {
    __shared__ float r0[512], r1[512];
    int t = threadIdx.x;
    r0[t] = part[t * 2 + 0];
    r1[t] = part[t * 2 + 1];
    __syncthreads();
    for (int s = 256; s > 0; s >>= 1) {
        if (t < s) { r0[t] += r0[t+s]; r1[t] += r1[t+s]; }
        __syncthreads();
    }
    if (t == 0) outp[0] = r0[0] / fmaxf(r1[0], 1.0f);
}

// ---------------- host orchestration ----------------------------------------
extern "C" void kernel_launch(void* const* d_in, const int* in_sizes, int n_in,
                              void* d_out, int out_size)
{
    const float* enc   = (const float*)d_in[0];
    const float* dsc   = (const float*)d_in[1];
    const int*   maskA = (const int*)  d_in[2];
    const int*   cand  = (const int*)  d_in[3];
    const int*   labels= (const int*)  d_in[4];
    const float* ipw   = (const float*)d_in[5];
    const float* ipb   = (const float*)d_in[6];
    const float* ow    = (const float*)d_in[7];
    const float* ob    = (const float*)d_in[8];
    const float* g1    = (const float*)d_in[9];
    const float* b1    = (const float*)d_in[10];
    const float* W1    = (const float*)d_in[11];
    const float* bb1   = (const float*)d_in[12];
    const float* W2    = (const float*)d_in[13];
    const float* bb2   = (const float*)d_in[14];
    const float* g2    = (const float*)d_in[15];
    const float* b2    = (const float*)d_in[16];
    const float* cw    = (const float*)d_in[17];
    const float* cb    = (const float*)d_in[18];

    float *A, *A1, *TMP, *V, *S, *PART;
    bf16 *Ahi,*Alo,*A1hi,*A1lo,*Dhi,*Dlo,*Qhi,*Qlo,*Khi,*Klo,*VThi,*VTlo;
    bf16 *Phi,*Plo,*CThi,*CTlo,*MIDhi,*MIDlo;
    bf16 *IPWhi,*IPWlo,*OWhi,*OWlo,*W1hi,*W1lo,*W2hi,*W2lo;
    cudaGetSymbolAddress((void**)&A, g_A);     cudaGetSymbolAddress((void**)&A1, g_A1);
    cudaGetSymbolAddress((void**)&TMP, g_TMP); cudaGetSymbolAddress((void**)&V, g_V);
    cudaGetSymbolAddress((void**)&S, g_S);     cudaGetSymbolAddress((void**)&PART, g_PART);
    cudaGetSymbolAddress((void**)&Ahi, g_Ahi); cudaGetSymbolAddress((void**)&Alo, g_Alo);
    cudaGetSymbolAddress((void**)&A1hi, g_A1hi); cudaGetSymbolAddress((void**)&A1lo, g_A1lo);
    cudaGetSymbolAddress((void**)&Dhi, g_Dhi); cudaGetSymbolAddress((void**)&Dlo, g_Dlo);
    cudaGetSymbolAddress((void**)&Qhi, g_Qhi); cudaGetSymbolAddress((void**)&Qlo, g_Qlo);
    cudaGetSymbolAddress((void**)&Khi, g_Khi); cudaGetSymbolAddress((void**)&Klo, g_Klo);
    cudaGetSymbolAddress((void**)&VThi, g_VThi); cudaGetSymbolAddress((void**)&VTlo, g_VTlo);
    cudaGetSymbolAddress((void**)&Phi, g_Phi); cudaGetSymbolAddress((void**)&Plo, g_Plo);
    cudaGetSymbolAddress((void**)&CThi, g_CThi); cudaGetSymbolAddress((void**)&CTlo, g_CTlo);
    cudaGetSymbolAddress((void**)&MIDhi, g_MIDhi); cudaGetSymbolAddress((void**)&MIDlo, g_MIDlo);
    cudaGetSymbolAddress((void**)&IPWhi, g_IPWhi); cudaGetSymbolAddress((void**)&IPWlo, g_IPWlo);
    cudaGetSymbolAddress((void**)&OWhi, g_OWhi); cudaGetSymbolAddress((void**)&OWlo, g_OWlo);
    cudaGetSymbolAddress((void**)&W1hi, g_W1hi); cudaGetSymbolAddress((void**)&W1lo, g_W1lo);
    cudaGetSymbolAddress((void**)&W2hi, g_W2hi); cudaGetSymbolAddress((void**)&W2lo, g_W2lo);

    // ---- one-time (per call) splits ----
    int nIPW = LNUM*3*EDIM*EDIM, nOW = LNUM*EDIM*EDIM;
    int nW1 = LNUM*FDIM*EDIM,    nW2 = LNUM*EDIM*FDIM;
    split_f<<<(nIPW+255)/256, 256>>>(ipw, IPWhi, IPWlo, nIPW);
    split_f<<<(nOW +255)/256, 256>>>(ow,  OWhi,  OWlo,  nOW);
    split_f<<<(nW1 +255)/256, 256>>>(W1,  W1hi,  W1lo,  nW1);
    split_f<<<(nW2 +255)/256, 256>>>(W2,  W2hi,  W2lo,  nW2);
    split_f<<<(BDIM*SBK*EDIM+255)/256, 256>>>(dsc, Dhi, Dlo, BDIM*SBK*EDIM);
    split_f<<<(MROWS*EDIM+255)/256, 256>>>(enc, Ahi, Alo, MROWS*EDIM);
    copy_f <<<(MROWS*EDIM+255)/256, 256>>>(enc, A, MROWS*EDIM);

    const float scaleS = 0.125f;   // 1/sqrt(64)
    dim3 gP (EDIM/128, MROWS/128, 1);      // proj / ffn2 / out-proj
    dim3 gF1(FDIM/128, MROWS/128, 1);      // ffn1
    dim3 gS (SBK/128, SAQ/128, BDIM*HNUM); // scores
    dim3 gC (1, SAQ/128, BDIM*HNUM);       // ctx (BN=64)
    dim3 gT (EDIM/32, MROWS/32, 1);
    dim3 bT (32, 8, 1);

    for (int l = 0; l < LNUM; l++) {
        const bf16 *wqh = IPWhi + (long)l*3*EDIM*EDIM, *wql = IPWlo + (long)l*3*EDIM*EDIM;
        const bf16 *wkh = wqh + EDIM*EDIM, *wkl = wql + EDIM*EDIM;
        const bf16 *wvh = wkh + EDIM*EDIM, *wvl = wkl + EDIM*EDIM;
        const float *bq = ipb + (long)l*3*EDIM, *bk = bq + EDIM, *bv = bk + EDIM;

        // Q/K: split-store bf16.  V: fp32 (for transpose_split).
        gemm_bf3<128><<<gP, 256>>>(Ahi, Alo, wqh, wql, bq, 0, Qhi, Qlo,
            EDIM, EDIM, EDIM, EDIM, 0,0,0,0,0,0,1, 1.0f, 1, 0);
        gemm_bf3<128><<<gP, 256>>>(Dhi, Dlo, wkh, wkl, bk, 0, Khi, Klo,
            EDIM, EDIM, EDIM, EDIM, 0,0,0,0,0,0,1, 1.0f, 1, 0);
        gemm_bf3<128><<<gP, 256>>>(Dhi, Dlo, wvh, wvl, bv, V, 0, 0,
            EDIM, EDIM, EDIM, EDIM, 0,0,0,0,0,0,1, 1.0f, 0, 0);
        transpose_split<<<gT, bT>>>(V, VThi, VTlo);

        // scores = scale * Q @ K^T  (per b,h: M=512,N=512,K=64)
        gemm_bf3<128><<<gS, 256>>>(Qhi, Qlo, Khi, Klo, 0, S, 0, 0,
            DHEAD, EDIM, EDIM, SBK,
            (long)SAQ*EDIM, DHEAD, (long)SBK*EDIM, DHEAD,
            (long)HNUM*SAQ*SBK, (long)SAQ*SBK, HNUM, scaleS, 0, 0);

        softmax512<<<BDIM*HNUM*SAQ, 256>>>(S, Phi, Plo);

        // ctx = P @ V  (TN against VT: M=512,N=64,K=512), split-store
        gemm_bf3<64><<<gC, 256>>>(Phi, Plo, VThi, VTlo, 0, 0, CThi, CTlo,
            SBK, SBK, MROWS, EDIM,
            (long)HNUM*SAQ*SBK, (long)SAQ*SBK,
            (long)SBK, (long)DHEAD*MROWS,
            (long)SAQ*EDIM, DHEAD, HNUM, 1.0f, 1, 0);

        // attn_out = ctx @ ow^T + ob  -> fp32 TMP
        gemm_bf3<128><<<gP, 256>>>(CThi, CTlo, OWhi + (long)l*EDIM*EDIM,
            OWlo + (long)l*EDIM*EDIM, ob + (long)l*EDIM, TMP, 0, 0,
            EDIM, EDIM, EDIM, EDIM, 0,0,0,0,0,0,1, 1.0f, 0, 0);

        add_ln<<<MROWS, 256>>>(A, TMP, g1 + (long)l*EDIM, b1 + (long)l*EDIM,
                               A1, A1hi, A1lo);

        // mid = relu(A1 @ W1^T + b1) -> split bf16
        gemm_bf3<128><<<gF1, 256>>>(A1hi, A1lo, W1hi + (long)l*FDIM*EDIM,
            W1lo + (long)l*FDIM*EDIM, bb1 + (long)l*FDIM, 0, MIDhi, MIDlo,
            EDIM, EDIM, EDIM, FDIM, 0,0,0,0,0,0,1, 1.0f, 1, 1);

        // ff = mid @ W2^T + b2 -> fp32 TMP
        gemm_bf3<128><<<gP, 256>>>(MIDhi, MIDlo, W2hi + (long)l*EDIM*FDIM,
            W2lo + (long)l*EDIM*FDIM, bb2 + (long)l*EDIM, TMP, 0, 0,
            FDIM, FDIM, FDIM, EDIM, 0,0,0,0,0,0,1, 1.0f, 0, 0);

        add_ln<<<MROWS, 256>>>(A1, TMP, g2 + (long)l*EDIM, b2 + (long)l*EDIM,
                               A, Ahi, Alo);
    }

    classify<<<MROWS/8, 256>>>(A, cw, cb, labels, maskA, cand, (float*)d_out, PART);
    finalize<<<1, 512>>>(PART, (float*)d_out);
}

// round 4
// speedup vs baseline: 2.3495x; 1.3343x over previous
#include <cuda_runtime.h>
#include <cuda_bf16.h>
#include <math.h>
#include <stdint.h>

// Problem dims
#define LNUM 9
#define BDIM 8
#define SAQ 512
#define SBK 512
#define EDIM 1024
#define HNUM 16
#define DHEAD 64
#define FDIM 4096
#define MROWS (BDIM*SAQ)          // 4096

typedef __nv_bfloat16 bf16;
typedef __nv_bfloat162 bf162;

// ---------------- scratch (device globals) ----------------------------------
__device__ float g_A  [MROWS*EDIM];
__device__ float g_A1 [MROWS*EDIM];
__device__ float g_TMP[MROWS*EDIM];
__device__ float g_V  [MROWS*EDIM];
__device__ float g_S  [(long)BDIM*HNUM*SAQ*SBK];
__device__ float g_PART[1024];

__device__ bf16 g_Ahi [MROWS*EDIM],  g_Alo [MROWS*EDIM];
__device__ bf16 g_A1hi[MROWS*EDIM],  g_A1lo[MROWS*EDIM];
__device__ bf16 g_Dhi [BDIM*SBK*EDIM], g_Dlo [BDIM*SBK*EDIM];
__device__ bf16 g_Qhi [MROWS*EDIM],  g_Qlo [MROWS*EDIM];
__device__ bf16 g_Khi [MROWS*EDIM],  g_Klo [MROWS*EDIM];
__device__ bf16 g_VThi[EDIM*MROWS],  g_VTlo[EDIM*MROWS];
__device__ bf16 g_Phi [(long)BDIM*HNUM*SAQ*SBK], g_Plo[(long)BDIM*HNUM*SAQ*SBK];
__device__ bf16 g_CThi[MROWS*EDIM],  g_CTlo[MROWS*EDIM];
__device__ bf16 g_MIDhi[(long)MROWS*FDIM], g_MIDlo[(long)MROWS*FDIM];
__device__ bf16 g_IPWhi[LNUM*3*EDIM*EDIM], g_IPWlo[LNUM*3*EDIM*EDIM];
__device__ bf16 g_OWhi [LNUM*EDIM*EDIM],   g_OWlo [LNUM*EDIM*EDIM];
__device__ bf16 g_W1hi [(long)LNUM*FDIM*EDIM], g_W1lo[(long)LNUM*FDIM*EDIM];
__device__ bf16 g_W2hi [(long)LNUM*EDIM*FDIM], g_W2lo[(long)LNUM*EDIM*FDIM];

// ---------------- helpers ----------------------------------------------------
__device__ __forceinline__ void split2(float v, bf16& h, bf16& l) {
    h = __float2bfloat16(v);
    l = __float2bfloat16(v - __bfloat162float(h));
}

__device__ __forceinline__ uint32_t smem_u32(const void* p) {
    uint32_t a;
    asm("{ .reg .u64 t; cvta.to.shared.u64 t, %1; cvt.u32.u64 %0, t; }"
        : "=r"(a) : "l"(p));
    return a;
}

#define CPA16(dst, src) \
    asm volatile("cp.async.cg.shared.global [%0], [%1], 16;" :: "r"(dst), "l"(src))
#define CPA_COMMIT() asm volatile("cp.async.commit_group;" ::: "memory")
#define CPA_WAIT1()  asm volatile("cp.async.wait_group 1;" ::: "memory")
#define CPA_WAIT0()  asm volatile("cp.async.wait_group 0;" ::: "memory")

__global__ void copy_f(const float* __restrict__ src, float* __restrict__ dst, int n) {
    int i = blockIdx.x * blockDim.x + threadIdx.x;
    if (i < n) dst[i] = src[i];
}

__global__ void split_f(const float* __restrict__ src, bf16* __restrict__ hi,
                        bf16* __restrict__ lo, int n) {
    int i = blockIdx.x * blockDim.x + threadIdx.x;
    if (i < n) { bf16 h, l; split2(src[i], h, l); hi[i] = h; lo[i] = l; }
}

// V [4096][1024] f32 -> VT [1024][4096] split bf16
__global__ void transpose_split(const float* __restrict__ V,
                                bf16* __restrict__ VThi, bf16* __restrict__ VTlo) {
    __shared__ float t[32][33];
    int bx = blockIdx.x * 32, by = blockIdx.y * 32;
    int tx = threadIdx.x, ty = threadIdx.y;
#pragma unroll
    for (int i = 0; i < 4; i++)
        t[ty + i*8][tx] = V[(long)(by + ty + i*8) * EDIM + bx + tx];
    __syncthreads();
#pragma unroll
    for (int i = 0; i < 4; i++) {
        float v = t[tx][ty + i*8];
        bf16 h, l; split2(v, h, l);
        long o = (long)(bx + ty + i*8) * MROWS + by + tx;
        VThi[o] = h; VTlo[o] = l;
    }
}

// ---------------- bf16x3 warp-MMA GEMM (TN), cp.async double-buffered --------
// C[m,n] = alpha * sum_k (Ahi+Alo)[m,k] * (Bhi+Blo)[n,k]  (+bias, relu)
// dropping the Alo*Blo term. BM=128, BK=32, BN template (128 or 64).
// mode 0: store fp32 to Cf.   mode 1: split-store bf16 to Chi/Clo.
__device__ __forceinline__ void mma16816(float* d, const unsigned* a, const unsigned* b) {
    asm volatile(
        "mma.sync.aligned.m16n8k16.row.col.f32.bf16.bf16.f32 "
        "{%0,%1,%2,%3},{%4,%5,%6,%7},{%8,%9},{%0,%1,%2,%3};"
        : "+f"(d[0]), "+f"(d[1]), "+f"(d[2]), "+f"(d[3])
        : "r"(a[0]), "r"(a[1]), "r"(a[2]), "r"(a[3]), "r"(b[0]), "r"(b[1]));
}

template<int BN>
__global__ void __launch_bounds__(256, 2) gemm_bf3(
    const bf16* __restrict__ Ahi_g, const bf16* __restrict__ Alo_g,
    const bf16* __restrict__ Bhi_g, const bf16* __restrict__ Blo_g,
    const float* __restrict__ bias,
    float* __restrict__ Cf, bf16* __restrict__ Chi, bf16* __restrict__ Clo,
    int K, int lda, int ldb, int ldc,
    long sAb, long sAh, long sBb, long sBh, long sCb, long sCh, int nH,
    float alpha, int mode, int relu)
{
    constexpr int KS  = 40;               // padded smem row stride (80B = 5*16B)
    constexpr int AST = 128 * KS;         // elems per A tile
    constexpr int BST = BN * KS;          // elems per B tile
    constexpr int STG = 2 * AST + 2 * BST;// elems per stage (Ahi,Alo,Bhi,Blo)
    constexpr int NT  = BN / 16;          // n-tiles (m16n8 pairs) per warp

    extern __shared__ bf16 sm[];
    uint32_t smb = smem_u32(sm);

    int bz = blockIdx.z;
    int bb = bz / nH, hh = bz % nH;
    const bf16* Ah = Ahi_g + bb * sAb + hh * sAh;
    const bf16* Al = Alo_g + bb * sAb + hh * sAh;
    const bf16* Bh = Bhi_g + bb * sBb + hh * sBh;
    const bf16* Bl = Blo_g + bb * sBb + hh * sBh;
    long cbase = bb * sCb + hh * sCh;

    int bm = blockIdx.y * 128, bn = blockIdx.x * BN;
    int tid = threadIdx.x;
    int wid = tid >> 5, lane = tid & 31;
    int wm = wid & 3, wn = wid >> 2;
    int mb = wm * 32, nb = wn * (BN / 2);
    int lr = lane >> 2, lc = (lane & 3) * 2;

    float acc[2][NT][4];
#pragma unroll
    for (int i = 0; i < 2; i++)
#pragma unroll
        for (int j = 0; j < NT; j++)
#pragma unroll
            for (int q = 0; q < 4; q++) acc[i][j][q] = 0.f;

    // ---- stage loader: (256 + 2*BN) rows x 4 chunks of 16B --------------
    auto load_stage = [&](int s, int kt) {
        uint32_t sb = smb + (uint32_t)s * (STG * 2);
#pragma unroll 4
        for (int i = tid; i < (256 + 2 * BN) * 4; i += 256) {
            int row = i >> 2, seg = (i & 3) << 3;     // seg in elements
            const bf16* src; uint32_t toff; int r;
            if (row < 256) {
                r = row & 127;
                src  = (row < 128 ? Ah : Al) + (long)(bm + r) * lda + kt + seg;
                toff = (row < 128) ? 0u : (uint32_t)AST;
            } else {
                int rb = row - 256;
                r = rb & (BN - 1);
                src  = (rb < BN ? Bh : Bl) + (long)(bn + r) * ldb + kt + seg;
                toff = (rb < BN) ? (uint32_t)(2 * AST) : (uint32_t)(2 * AST + BST);
            }
            uint32_t dst = sb + (toff + (uint32_t)(r * KS + seg)) * 2u;
            CPA16(dst, src);
        }
        CPA_COMMIT();
    };

    const int NC = K >> 5;                 // BK = 32
    load_stage(0, 0);

    for (int c = 0; c < NC; c++) {
        int s = c & 1;
        if (c + 1 < NC) { load_stage(s ^ 1, (c + 1) << 5); CPA_WAIT1(); }
        else            { CPA_WAIT0(); }
        __syncthreads();

        const bf16* sAh = sm + s * STG;
        const bf16* sAl = sAh + AST;
        const bf16* sBh = sAh + 2 * AST;
        const bf16* sBl = sBh + BST;

#pragma unroll
        for (int ks = 0; ks < 2; ks++) {
            int k0 = ks * 16;
            unsigned aH[2][4], aL[2][4];
#pragma unroll
            for (int mt = 0; mt < 2; mt++) {
                int o = (mb + mt * 16 + lr) * KS + k0 + lc;
                aH[mt][0] = *(const unsigned*)&sAh[o];
                aH[mt][1] = *(const unsigned*)&sAh[o + 8 * KS];
                aH[mt][2] = *(const unsigned*)&sAh[o + 8];
                aH[mt][3] = *(const unsigned*)&sAh[o + 8 * KS + 8];
                aL[mt][0] = *(const unsigned*)&sAl[o];
                aL[mt][1] = *(const unsigned*)&sAl[o + 8 * KS];
                aL[mt][2] = *(const unsigned*)&sAl[o + 8];
                aL[mt][3] = *(const unsigned*)&sAl[o + 8 * KS + 8];
            }
#pragma unroll
            for (int nc = 0; nc < NT; nc += 4) {
                unsigned bH[4][2], bL[4][2];
#pragma unroll
                for (int j = 0; j < 4; j++) {
                    int o = (nb + (nc + j) * 8 + lr) * KS + k0 + lc;
                    bH[j][0] = *(const unsigned*)&sBh[o];
                    bH[j][1] = *(const unsigned*)&sBh[o + 8];
                    bL[j][0] = *(const unsigned*)&sBl[o];
                    bL[j][1] = *(const unsigned*)&sBl[o + 8];
                }
#pragma unroll
                for (int mt = 0; mt < 2; mt++)
#pragma unroll
                    for (int j = 0; j < 4; j++) {
                        mma16816(acc[mt][nc + j], aH[mt], bH[j]);   // hi*hi
                        mma16816(acc[mt][nc + j], aH[mt], bL[j]);   // hi*lo
                        mma16816(acc[mt][nc + j], aL[mt], bH[j]);   // lo*hi
                    }
            }
        }
        __syncthreads();
    }

    // ---- epilogue ----
#pragma unroll
    for (int mt = 0; mt < 2; mt++) {
#pragma unroll
        for (int nt = 0; nt < NT; nt++) {
            int gm = bm + mb + mt * 16 + lr;
            int gn = bn + nb + nt * 8 + lc;
            float v0 = acc[mt][nt][0] * alpha;
            float v1 = acc[mt][nt][1] * alpha;
            float v2 = acc[mt][nt][2] * alpha;
            float v3 = acc[mt][nt][3] * alpha;
            if (bias) {
                float b0 = bias[gn], b1 = bias[gn + 1];
                v0 += b0; v1 += b1; v2 += b0; v3 += b1;
            }
            if (relu) {
                v0 = fmaxf(v0, 0.f); v1 = fmaxf(v1, 0.f);
                v2 = fmaxf(v2, 0.f); v3 = fmaxf(v3, 0.f);
            }
            long o0 = cbase + (long)gm * ldc + gn;
            long o1 = cbase + (long)(gm + 8) * ldc + gn;
            if (mode == 0) {
                float2 r0; r0.x = v0; r0.y = v1;
                float2 r1; r1.x = v2; r1.y = v3;
                *(float2*)(Cf + o0) = r0;
                *(float2*)(Cf + o1) = r1;
            } else {
                bf16 h0, l0, h1, l1;
                split2(v0, h0, l0); split2(v1, h1, l1);
                *(bf162*)(Chi + o0) = __halves2bfloat162(h0, h1);
                *(bf162*)(Clo + o0) = __halves2bfloat162(l0, l1);
                split2(v2, h0, l0); split2(v3, h1, l1);
                *(bf162*)(Chi + o1) = __halves2bfloat162(h0, h1);
                *(bf162*)(Clo + o1) = __halves2bfloat162(l0, l1);
            }
        }
    }
}

// ---------------- softmax over rows of 512 -> split bf16 --------------------
__global__ void softmax512(const float* __restrict__ S,
                           bf16* __restrict__ Phi, bf16* __restrict__ Plo) {
    const float* p = S + (long)blockIdx.x * 512;
    int t = threadIdx.x;
    float x0 = p[t], x1 = p[t + 256];
    __shared__ float red[256];
    red[t] = fmaxf(x0, x1); __syncthreads();
    for (int s = 128; s > 0; s >>= 1) {
        if (t < s) red[t] = fmaxf(red[t], red[t + s]);
        __syncthreads();
    }
    float m = red[0]; __syncthreads();
    float e0 = expf(x0 - m), e1 = expf(x1 - m);
    red[t] = e0 + e1; __syncthreads();
    for (int s = 128; s > 0; s >>= 1) {
        if (t < s) red[t] += red[t + s];
        __syncthreads();
    }
    float inv = 1.f / red[0];
    long o = (long)blockIdx.x * 512 + t;
    bf16 h, l;
    split2(e0 * inv, h, l); Phi[o] = h;       Plo[o] = l;
    split2(e1 * inv, h, l); Phi[o + 256] = h; Plo[o + 256] = l;
}

// ---------------- fused residual + LayerNorm (+ split outputs) --------------
__global__ void add_ln(const float* __restrict__ X, const float* __restrict__ R,
                       const float* __restrict__ g, const float* __restrict__ b,
                       float* __restrict__ Y, bf16* __restrict__ Yhi, bf16* __restrict__ Ylo)
{
    long row = blockIdx.x;
    const float* x = X + row * EDIM;
    const float* r = R + row * EDIM;
    int t = threadIdx.x;
    float v[4];
#pragma unroll
    for (int i = 0; i < 4; i++) v[i] = x[t + i*256] + r[t + i*256];
    __shared__ float red[256];
    red[t] = v[0] + v[1] + v[2] + v[3]; __syncthreads();
    for (int s = 128; s > 0; s >>= 1) { if (t < s) red[t] += red[t+s]; __syncthreads(); }
    float mean = red[0] * (1.f / EDIM); __syncthreads();
    float q = 0.f;
#pragma unroll
    for (int i = 0; i < 4; i++) { float d = v[i] - mean; q = fmaf(d, d, q); }
    red[t] = q; __syncthreads();
    for (int s = 128; s > 0; s >>= 1) { if (t < s) red[t] += red[t+s]; __syncthreads(); }
    float inv = rsqrtf(red[0] * (1.f / EDIM) + 1e-5f);
#pragma unroll
    for (int i = 0; i < 4; i++) {
        int c = t + i*256;
        float y = (v[i] - mean) * inv * g[c] + b[c];
        Y[row * EDIM + c] = y;
        bf16 h, l; split2(y, h, l);
        Yhi[row * EDIM + c] = h;
        Ylo[row * EDIM + c] = l;
    }
}

// ---------------- classifier + loss ------------------------------------------
__global__ void classify(const float* __restrict__ Aout, const float* __restrict__ cw,
                         const float* __restrict__ cb, const int* __restrict__ labels,
                         const int* __restrict__ maskA, const int* __restrict__ cand,
                         float* __restrict__ outp, float* __restrict__ part)
{
    int warp = threadIdx.x >> 5, lane = threadIdx.x & 31;
    int row = blockIdx.x * 8 + warp;
    const float* a = Aout + (long)row * EDIM;
    float d0 = 0.f, d1 = 0.f;
    for (int e = lane; e < EDIM; e += 32) {
        float av = a[e];
        d0 = fmaf(av, cw[e], d0);
        d1 = fmaf(av, cw[EDIM + e], d1);
    }
#pragma unroll
    for (int o = 16; o > 0; o >>= 1) {
        d0 += __shfl_down_sync(0xffffffffu, d0, o);
        d1 += __shfl_down_sync(0xffffffffu, d1, o);
    }
    __shared__ float pw[8][2];
    if (lane == 0) {
        float e0 = d0 + cb[0], e1 = d1 + cb[1];
        int lb = labels[row];
        float mx = fmaxf(e0, e1);
        float lse = mx + logf(expf(e0 - mx) + expf(e1 - mx));
        float ce = lse - ((lb == 1) ? e1 : e0);
        float w = (lb == 1) ? 5.0f : 1.0f;
        float valid = (maskA[row] == 1) ? 1.0f : 0.0f;
        pw[warp][0] = ce * w * valid;
        pw[warp][1] = valid;
        int pred1 = (e1 > e0) ? 1 : 0;
        outp[1 + row] = ((cand[row] == 1) && pred1) ? 1.0f : 0.0f;
    }
    __syncthreads();
    if (threadIdx.x == 0) {
        float s0 = 0.f, s1 = 0.f;
#pragma unroll
        for (int i = 0; i < 8; i++) { s0 += pw[i][0]; s1 += pw[i][1]; }
        part[blockIdx.x * 2 + 0] = s0;
        part[blockIdx.x * 2 + 1] = s1;
    }
}

__global__ void finalize(const float* __restrict__ part, float* __restrict__ outp) {
    __shared__ float r0[512], r1[512];
    int t = threadIdx.x;
    r0[t] = part[t * 2 + 0];
    r1[t] = part[t * 2 + 1];
    __syncthreads();
    for (int s = 256; s > 0; s >>= 1) {
        if (t < s) { r0[t] += r0[t+s]; r1[t] += r1[t+s]; }
        __syncthreads();
    }
    if (t == 0) outp[0] = r0[0] / fmaxf(r1[0], 1.0f);
}

// ---------------- host orchestration ----------------------------------------
extern "C" void kernel_launch(void* const* d_in, const int* in_sizes, int n_in,
                              void* d_out, int out_size)
{
    const float* enc   = (const float*)d_in[0];
    const float* dsc   = (const float*)d_in[1];
    const int*   maskA = (const int*)  d_in[2];
    const int*   cand  = (const int*)  d_in[3];
    const int*   labels= (const int*)  d_in[4];
    const float* ipw   = (const float*)d_in[5];
    const float* ipb   = (const float*)d_in[6];
    const float* ow    = (const float*)d_in[7];
    const float* ob    = (const float*)d_in[8];
    const float* g1    = (const float*)d_in[9];
    const float* b1    = (const float*)d_in[10];
    const float* W1    = (const float*)d_in[11];
    const float* bb1   = (const float*)d_in[12];
    const float* W2    = (const float*)d_in[13];
    const float* bb2   = (const float*)d_in[14];
    const float* g2    = (const float*)d_in[15];
    const float* b2    = (const float*)d_in[16];
    const float* cw    = (const float*)d_in[17];
    const float* cb    = (const float*)d_in[18];

    float *A, *A1, *TMP, *V, *S, *PART;
    bf16 *Ahi,*Alo,*A1hi,*A1lo,*Dhi,*Dlo,*Qhi,*Qlo,*Khi,*Klo,*VThi,*VTlo;
    bf16 *Phi,*Plo,*CThi,*CTlo,*MIDhi,*MIDlo;
    bf16 *IPWhi,*IPWlo,*OWhi,*OWlo,*W1hi,*W1lo,*W2hi,*W2lo;
    cudaGetSymbolAddress((void**)&A, g_A);     cudaGetSymbolAddress((void**)&A1, g_A1);
    cudaGetSymbolAddress((void**)&TMP, g_TMP); cudaGetSymbolAddress((void**)&V, g_V);
    cudaGetSymbolAddress((void**)&S, g_S);     cudaGetSymbolAddress((void**)&PART, g_PART);
    cudaGetSymbolAddress((void**)&Ahi, g_Ahi); cudaGetSymbolAddress((void**)&Alo, g_Alo);
    cudaGetSymbolAddress((void**)&A1hi, g_A1hi); cudaGetSymbolAddress((void**)&A1lo, g_A1lo);
    cudaGetSymbolAddress((void**)&Dhi, g_Dhi); cudaGetSymbolAddress((void**)&Dlo, g_Dlo);
    cudaGetSymbolAddress((void**)&Qhi, g_Qhi); cudaGetSymbolAddress((void**)&Qlo, g_Qlo);
    cudaGetSymbolAddress((void**)&Khi, g_Khi); cudaGetSymbolAddress((void**)&Klo, g_Klo);
    cudaGetSymbolAddress((void**)&VThi, g_VThi); cudaGetSymbolAddress((void**)&VTlo, g_VTlo);
    cudaGetSymbolAddress((void**)&Phi, g_Phi); cudaGetSymbolAddress((void**)&Plo, g_Plo);
    cudaGetSymbolAddress((void**)&CThi, g_CThi); cudaGetSymbolAddress((void**)&CTlo, g_CTlo);
    cudaGetSymbolAddress((void**)&MIDhi, g_MIDhi); cudaGetSymbolAddress((void**)&MIDlo, g_MIDlo);
    cudaGetSymbolAddress((void**)&IPWhi, g_IPWhi); cudaGetSymbolAddress((void**)&IPWlo, g_IPWlo);
    cudaGetSymbolAddress((void**)&OWhi, g_OWhi); cudaGetSymbolAddress((void**)&OWlo, g_OWlo);
    cudaGetSymbolAddress((void**)&W1hi, g_W1hi); cudaGetSymbolAddress((void**)&W1lo, g_W1lo);
    cudaGetSymbolAddress((void**)&W2hi, g_W2hi); cudaGetSymbolAddress((void**)&W2lo, g_W2lo);

    // dynamic smem: 2 stages of (2*128 + 2*BN) rows * 40 bf16
    const int SMEM128 = 2 * (2*128*40 + 2*128*40) * 2;   // 81920 B
    const int SMEM64  = 2 * (2*128*40 + 2*64*40)  * 2;   // 61440 B
    static int attr_done = 0;
    if (!attr_done) {
        cudaFuncSetAttribute(gemm_bf3<128>, cudaFuncAttributeMaxDynamicSharedMemorySize, SMEM128);
        cudaFuncSetAttribute(gemm_bf3<64>,  cudaFuncAttributeMaxDynamicSharedMemorySize, SMEM64);
        attr_done = 1;
    }

    // ---- per-call splits ----
    int nIPW = LNUM*3*EDIM*EDIM, nOW = LNUM*EDIM*EDIM;
    int nW1 = LNUM*FDIM*EDIM,    nW2 = LNUM*EDIM*FDIM;
    split_f<<<(nIPW+255)/256, 256>>>(ipw, IPWhi, IPWlo, nIPW);
    split_f<<<(nOW +255)/256, 256>>>(ow,  OWhi,  OWlo,  nOW);
    split_f<<<(nW1 +255)/256, 256>>>(W1,  W1hi,  W1lo,  nW1);
    split_f<<<(nW2 +255)/256, 256>>>(W2,  W2hi,  W2lo,  nW2);
    split_f<<<(BDIM*SBK*EDIM+255)/256, 256>>>(dsc, Dhi, Dlo, BDIM*SBK*EDIM);
    split_f<<<(MROWS*EDIM+255)/256, 256>>>(enc, Ahi, Alo, MROWS*EDIM);
    copy_f <<<(MROWS*EDIM+255)/256, 256>>>(enc, A, MROWS*EDIM);

    const float scaleS = 0.125f;   // 1/sqrt(64)
    dim3 gP (EDIM/128, MROWS/128, 1);      // proj / ffn2 / out-proj
    dim3 gF1(FDIM/128, MROWS/128, 1);      // ffn1
    dim3 gS (SBK/128, SAQ/128, BDIM*HNUM); // scores
    dim3 gC (1, SAQ/128, BDIM*HNUM);       // ctx (BN=64)
    dim3 gT (EDIM/32, MROWS/32, 1);
    dim3 bT (32, 8, 1);

    for (int l = 0; l < LNUM; l++) {
        const bf16 *wqh = IPWhi + (long)l*3*EDIM*EDIM, *wql = IPWlo + (long)l*3*EDIM*EDIM;
        const bf16 *wkh = wqh + EDIM*EDIM, *wkl = wql + EDIM*EDIM;
        const bf16 *wvh = wkh + EDIM*EDIM, *wvl = wkl + EDIM*EDIM;
        const float *bq = ipb + (long)l*3*EDIM, *bk = bq + EDIM, *bv = bk + EDIM;

        // Q/K: split-store bf16.  V: fp32 (for transpose_split).
        gemm_bf3<128><<<gP, 256, SMEM128>>>(Ahi, Alo, wqh, wql, bq, 0, Qhi, Qlo,
            EDIM, EDIM, EDIM, EDIM, 0,0,0,0,0,0,1, 1.0f, 1, 0);
        gemm_bf3<128><<<gP, 256, SMEM128>>>(Dhi, Dlo, wkh, wkl, bk, 0, Khi, Klo,
            EDIM, EDIM, EDIM, EDIM, 0,0,0,0,0,0,1, 1.0f, 1, 0);
        gemm_bf3<128><<<gP, 256, SMEM128>>>(Dhi, Dlo, wvh, wvl, bv, V, 0, 0,
            EDIM, EDIM, EDIM, EDIM, 0,0,0,0,0,0,1, 1.0f, 0, 0);
        transpose_split<<<gT, bT>>>(V, VThi, VTlo);

        // scores = scale * Q @ K^T  (per b,h: M=512,N=512,K=64)
        gemm_bf3<128><<<gS, 256, SMEM128>>>(Qhi, Qlo, Khi, Klo, 0, S, 0, 0,
            DHEAD, EDIM, EDIM, SBK,
            (long)SAQ*EDIM, DHEAD, (long)SBK*EDIM, DHEAD,
            (long)HNUM*SAQ*SBK, (long)SAQ*SBK, HNUM, scaleS, 0, 0);

        softmax512<<<BDIM*HNUM*SAQ, 256>>>(S, Phi, Plo);

        // ctx = P @ V  (TN vs VT: per b,h M=512,N=64,K=512), split-store
        gemm_bf3<64><<<gC, 256, SMEM64>>>(Phi, Plo, VThi, VTlo, 0, 0, CThi, CTlo,
            SBK, SBK, MROWS, EDIM,
            (long)HNUM*SAQ*SBK, (long)SAQ*SBK,
            (long)SBK, (long)DHEAD*MROWS,
            (long)SAQ*EDIM, DHEAD, HNUM, 1.0f, 1, 0);

        // attn_out = ctx @ ow^T + ob  -> fp32 TMP
        gemm_bf3<128><<<gP, 256, SMEM128>>>(CThi, CTlo, OWhi + (long)l*EDIM*EDIM,
            OWlo + (long)l*EDIM*EDIM, ob + (long)l*EDIM, TMP, 0, 0,
            EDIM, EDIM, EDIM, EDIM, 0,0,0,0,0,0,1, 1.0f, 0, 0);

        add_ln<<<MROWS, 256>>>(A, TMP, g1 + (long)l*EDIM, b1 + (long)l*EDIM,
                               A1, A1hi, A1lo);

        // mid = relu(A1 @ W1^T + b1) -> split bf16
        gemm_bf3<128><<<gF1, 256, SMEM128>>>(A1hi, A1lo, W1hi + (long)l*FDIM*EDIM,
            W1lo + (long)l*FDIM*EDIM, bb1 + (long)l*FDIM, 0, MIDhi, MIDlo,
            EDIM, EDIM, EDIM, FDIM, 0,0,0,0,0,0,1, 1.0f, 1, 1);

        // ff = mid @ W2^T + b2 -> fp32 TMP
        gemm_bf3<128><<<gP, 256, SMEM128>>>(MIDhi, MIDlo, W2hi + (long)l*EDIM*FDIM,
            W2lo + (long)l*EDIM*FDIM, bb2 + (long)l*EDIM, TMP, 0, 0,
            FDIM, FDIM, FDIM, EDIM, 0,0,0,0,0,0,1, 1.0f, 0, 0);

        add_ln<<<MROWS, 256>>>(A1, TMP, g2 + (long)l*EDIM, b2 + (long)l*EDIM,
                               A, Ahi, Alo);
    }

    classify<<<MROWS/8, 256>>>(A, cw, cb, labels, maskA, cand, (float*)d_out, PART);
    finalize<<<1, 512>>>(PART, (float*)d_out);
}